// round 3
// baseline (speedup 1.0000x reference)
#include <cuda_runtime.h>
#include <cuda_fp16.h>
#include <cstdint>

// ---------------------------------------------------------------------------
// Problem constants
// ---------------------------------------------------------------------------
#define N_TABLES 64
#define VOCAB    1024
#define D_EA     128
#define D_CONT   129
#define MAXDAY   3650
#define P129H    132          // half stride for pe129 rows: 264B, 8B-aligned

// ---------------------------------------------------------------------------
// Scratch (device globals; no allocation allowed)
// ---------------------------------------------------------------------------
__device__ __align__(16) __half g_pe129h[MAXDAY * P129H];   // ~0.96 MB
__device__ __align__(16) __half g_pe128h[MAXDAY * D_EA];    // ~0.93 MB

// ---------------------------------------------------------------------------
// PE table generation, fp16. One thread per (day, k-pair): sincosf once,
// store (sin, cos) as half2. Angle reduced mod 2*pi in double so accuracy
// holds for day*1 up to 3650 even under fast-math sinf.
// pairs 0..64   -> pe129 (d=129), pair 64 stores sin only (k=128)
// pairs 65..128 -> pe128 (d=128)
// ---------------------------------------------------------------------------
__global__ void k_pe() {
    int tid = blockIdx.x * blockDim.x + threadIdx.x;
    const int PAIRS = 65 + 64;                 // 129 per day
    if (tid >= MAXDAY * PAIRS) return;
    int day  = tid / PAIRS;
    int pair = tid - day * PAIRS;
    bool is129 = pair < 65;
    int j = is129 ? pair : pair - 65;
    int d = is129 ? D_CONT : D_EA;

    const double TWO_PI     = 6.283185307179586476925286766559;
    const double INV_TWO_PI = 0.15915494309189533576888376337251;

    double invdiv = pow(10000.0, -(double)(2 * j) / (double)d);
    double ang = (double)day * invdiv;
    double r   = ang - rint(ang * INV_TWO_PI) * TWO_PI;
    float  f   = (float)r;
    float s, c;
    sincosf(f, &s, &c);

    if (is129) {
        if (j == 64) {
            g_pe129h[day * P129H + 128] = __float2half(s);   // k=128, even -> sin
        } else {
            *reinterpret_cast<__half2*>(&g_pe129h[day * P129H + 2 * j]) =
                __floats2half2_rn(s, c);
        }
    } else {
        *reinterpret_cast<__half2*>(&g_pe128h[day * D_EA + 2 * j]) =
            __floats2half2_rn(s, c);
    }
}

// ---------------------------------------------------------------------------
// Continuous branch: one warp per node, 129 outputs.
// Coalesced mapping k = lane + 32*j; PE read as scalar halves (same L2
// sectors as vector loads, tiny extra L1 wavefronts).
// ---------------------------------------------------------------------------
__global__ void k_cont(const int* __restrict__ ids,
                       const float* __restrict__ vals,
                       const int* __restrict__ days,
                       const float* __restrict__ ea,
                       float* __restrict__ out, int n) {
    int w    = (blockIdx.x * blockDim.x + threadIdx.x) >> 5;
    int lane = threadIdx.x & 31;
    if (w >= n) return;
    int id  = __ldg(ids  + w);
    int day = __ldg(days + w);
    const float*  earow = ea + id * D_EA;
    const __half* perow = g_pe129h + day * P129H;
    float* o = out + (long long)w * D_CONT;
#pragma unroll
    for (int j = 0; j < 4; j++) {
        int k = lane + 32 * j;
        o[k] = __ldg(earow + k) + __half2float(perow[k]);
    }
    if (lane == 0) o[D_EA] = __ldg(vals + w) + __half2float(perow[D_EA]);
}

// ---------------------------------------------------------------------------
// Categorical branch: one warp per node, 128 outputs, float4 end-to-end.
// PE row = 256B (8B-aligned); lane loads 4 halves as one uint2.
// ---------------------------------------------------------------------------
__global__ void k_categ(const int* __restrict__ ids,
                        const int* __restrict__ vocab,
                        const int* __restrict__ days,
                        const float4* __restrict__ ea4,
                        const float4* __restrict__ tab4,
                        float4* __restrict__ out4, int n) {
    int w    = (blockIdx.x * blockDim.x + threadIdx.x) >> 5;
    int lane = threadIdx.x & 31;
    if (w >= n) return;
    int id  = __ldg(ids   + w);
    int v   = __ldg(vocab + w);
    int day = __ldg(days  + w);

    float4 a = __ldg(ea4 + id * 32 + lane);
    float4 b = __ldg(tab4 + ((long long)id * VOCAB + v) * 32 + lane);

    uint2 pbits = *(reinterpret_cast<const uint2*>(g_pe128h) + day * 32 + lane);
    __half2 p01 = *reinterpret_cast<__half2*>(&pbits.x);
    __half2 p23 = *reinterpret_cast<__half2*>(&pbits.y);
    float2 f01 = __half22float2(p01);
    float2 f23 = __half22float2(p23);

    float4 r;
    r.x = a.x + b.x + f01.x;
    r.y = a.y + b.y + f01.y;
    r.z = a.z + b.z + f23.x;
    r.w = a.w + b.w + f23.y;
    out4[(long long)w * 32 + lane] = r;
}

// Scalar fallback if the categ output offset is not 16B aligned (n % 4 != 0).
__global__ void k_categ_scalar(const int* __restrict__ ids,
                               const int* __restrict__ vocab,
                               const int* __restrict__ days,
                               const float* __restrict__ ea,
                               const float* __restrict__ tab,
                               float* __restrict__ out, int n) {
    int w    = (blockIdx.x * blockDim.x + threadIdx.x) >> 5;
    int lane = threadIdx.x & 31;
    if (w >= n) return;
    int id  = __ldg(ids   + w);
    int v   = __ldg(vocab + w);
    int day = __ldg(days  + w);
    const float*  earow = ea + id * D_EA;
    const float*  trow  = tab + ((long long)id * VOCAB + v) * D_EA;
    const __half* perow = g_pe128h + day * D_EA;
    float* o = out + (long long)w * D_EA;
#pragma unroll
    for (int j = 0; j < 4; j++) {
        int k = lane + 32 * j;
        o[k] = __ldg(earow + k) + __ldg(trow + k) + __half2float(perow[k]);
    }
}

// ---------------------------------------------------------------------------
// Launch
// ---------------------------------------------------------------------------
extern "C" void kernel_launch(void* const* d_in, const int* in_sizes, int n_in,
                              void* d_out, int out_size) {
    const int*   cont_ids   = (const int*)  d_in[0];
    const float* cont_vals  = (const float*)d_in[1];
    const int*   cont_days  = (const int*)  d_in[2];
    const int*   categ_ids  = (const int*)  d_in[3];
    const int*   categ_voc  = (const int*)  d_in[4];
    const int*   categ_days = (const int*)  d_in[5];
    const float* ea_table   = (const float*)d_in[6];
    const float* categ_tab  = (const float*)d_in[7];

    const int n = in_sizes[0];

    float* out       = (float*)d_out;
    float* out_categ = out + (long long)n * D_CONT;

    // PE tables (fp16), regenerated every call (deterministic).
    {
        int total = MAXDAY * (65 + 64);
        k_pe<<<(total + 255) / 256, 256>>>();
    }

    int blocks = (n + 7) / 8;
    k_cont<<<blocks, 256>>>(cont_ids, cont_vals, cont_days, ea_table, out, n);

    bool aligned = ((((long long)n * D_CONT) & 3) == 0) &&
                   ((((unsigned long long)(size_t)out_categ) & 15ULL) == 0ULL);
    if (aligned) {
        k_categ<<<blocks, 256>>>(categ_ids, categ_voc, categ_days,
                                 (const float4*)ea_table,
                                 (const float4*)categ_tab,
                                 (float4*)out_categ, n);
    } else {
        k_categ_scalar<<<blocks, 256>>>(categ_ids, categ_voc, categ_days,
                                        ea_table, categ_tab, out_categ, n);
    }
}

// round 4
// speedup vs baseline: 1.2104x; 1.2104x over previous
#include <cuda_runtime.h>
#include <cuda_fp16.h>
#include <cstdint>

// ---------------------------------------------------------------------------
// Problem constants
// ---------------------------------------------------------------------------
#define N_TABLES 64
#define VOCAB    1024
#define D_EA     128
#define D_CONT   129
#define MAXDAY   3650
#define P129     132          // padded float stride for pe129 rows (16B align)

// ---------------------------------------------------------------------------
// Scratch (device globals; no allocation allowed)
// ---------------------------------------------------------------------------
// theta_q[p]: angle increment per day, in units of 2^-32 turns (fixed point).
// p in [0,65)   -> pe129 pairs (j = p),      d = 129
// p in [65,129) -> pe128 pairs (j = p - 65), d = 128
__device__ unsigned int g_theta_q[129];
__device__ __align__(16) float g_pe129[MAXDAY * P129];   // ~1.93 MB
__device__ __align__(16) float g_pe128[MAXDAY * D_EA];   // ~1.87 MB

// ---------------------------------------------------------------------------
// Stage 1: fixed-point angle increments. Double pow runs only 129 times.
// theta = (10000^(-2j/d)) / (2*pi) mod 1, quantized to 2^-32 turns.
// ---------------------------------------------------------------------------
__global__ void k_theta() {
    int p = threadIdx.x;
    if (p >= 129) return;
    bool is129 = p < 65;
    int j = is129 ? p : p - 65;
    int d = is129 ? D_CONT : D_EA;
    const double INV_TWO_PI = 0.15915494309189533576888376337251;
    double invdiv = pow(10000.0, -(double)(2 * j) / (double)d);
    double turns  = invdiv * INV_TWO_PI;          // in (0, 0.16]
    double frac   = turns - floor(turns);         // already < 1
    unsigned long long q = (unsigned long long)(frac * 4294967296.0 + 0.5);
    g_theta_q[p] = (unsigned int)q;               // mod 2^32
}

// ---------------------------------------------------------------------------
// Stage 2: PE tables, all-fp32 integer range reduction.
// One thread per (day, pair): q = day*theta_q (uint32 wrap == mod 2pi exact),
// signed reinterpret -> turns in [-0.5, 0.5), f = q_s * (2pi * 2^-32),
// sincosf on |f| <= pi.
// ---------------------------------------------------------------------------
__global__ void k_pe() {
    int tid = blockIdx.x * blockDim.x + threadIdx.x;
    const int PAIRS = 129;
    if (tid >= MAXDAY * PAIRS) return;
    int day  = tid / PAIRS;
    int pair = tid - day * PAIRS;

    unsigned int q = (unsigned int)day * g_theta_q[pair];
    const float SCALE = 1.46291807926715968e-09f;   // 2*pi / 2^32
    float f = (float)(int)q * SCALE;                // [-pi, pi)
    float s, c;
    sincosf(f, &s, &c);

    if (pair < 65) {
        int j = pair;
        if (j == 64) {
            g_pe129[day * P129 + 128] = s;          // k=128 (even) -> sin
        } else {
            *reinterpret_cast<float2*>(&g_pe129[day * P129 + 2 * j]) =
                make_float2(s, c);
        }
    } else {
        int j = pair - 65;
        *reinterpret_cast<float2*>(&g_pe128[day * D_EA + 2 * j]) =
            make_float2(s, c);
    }
}

// ---------------------------------------------------------------------------
// Continuous branch: one warp per node, 129 outputs (proven R2 kernel).
// ---------------------------------------------------------------------------
__global__ void k_cont(const int* __restrict__ ids,
                       const float* __restrict__ vals,
                       const int* __restrict__ days,
                       const float* __restrict__ ea,
                       float* __restrict__ out, int n) {
    int w    = (blockIdx.x * blockDim.x + threadIdx.x) >> 5;
    int lane = threadIdx.x & 31;
    if (w >= n) return;
    int id  = __ldg(ids  + w);
    int day = __ldg(days + w);
    const float* earow = ea + id * D_EA;
    const float* perow = g_pe129 + day * P129;
    float* o = out + (long long)w * D_CONT;
#pragma unroll
    for (int j = 0; j < 4; j++) {
        int k = lane + 32 * j;
        o[k] = __ldg(earow + k) + perow[k];
    }
    if (lane == 0) o[D_EA] = __ldg(vals + w) + perow[D_EA];
}

// ---------------------------------------------------------------------------
// Categorical branch: one warp per node, 128 outputs, float4 (proven R2).
// ---------------------------------------------------------------------------
__global__ void k_categ(const int* __restrict__ ids,
                        const int* __restrict__ vocab,
                        const int* __restrict__ days,
                        const float4* __restrict__ ea4,
                        const float4* __restrict__ tab4,
                        float4* __restrict__ out4, int n) {
    int w    = (blockIdx.x * blockDim.x + threadIdx.x) >> 5;
    int lane = threadIdx.x & 31;
    if (w >= n) return;
    int id  = __ldg(ids   + w);
    int v   = __ldg(vocab + w);
    int day = __ldg(days  + w);

    float4 a = __ldg(ea4 + id * 32 + lane);
    float4 b = __ldg(tab4 + ((long long)id * VOCAB + v) * 32 + lane);
    const float4* pe4 = reinterpret_cast<const float4*>(g_pe128) + day * 32;
    float4 p = pe4[lane];

    float4 r;
    r.x = a.x + b.x + p.x;
    r.y = a.y + b.y + p.y;
    r.z = a.z + b.z + p.z;
    r.w = a.w + b.w + p.w;
    out4[(long long)w * 32 + lane] = r;
}

// Scalar fallback if the categ output offset is not 16B aligned (n % 4 != 0).
__global__ void k_categ_scalar(const int* __restrict__ ids,
                               const int* __restrict__ vocab,
                               const int* __restrict__ days,
                               const float* __restrict__ ea,
                               const float* __restrict__ tab,
                               float* __restrict__ out, int n) {
    int w    = (blockIdx.x * blockDim.x + threadIdx.x) >> 5;
    int lane = threadIdx.x & 31;
    if (w >= n) return;
    int id  = __ldg(ids   + w);
    int v   = __ldg(vocab + w);
    int day = __ldg(days  + w);
    const float* earow = ea + id * D_EA;
    const float* trow  = tab + ((long long)id * VOCAB + v) * D_EA;
    const float* perow = g_pe128 + day * D_EA;
    float* o = out + (long long)w * D_EA;
#pragma unroll
    for (int j = 0; j < 4; j++) {
        int k = lane + 32 * j;
        o[k] = __ldg(earow + k) + __ldg(trow + k) + perow[k];
    }
}

// ---------------------------------------------------------------------------
// Launch
// ---------------------------------------------------------------------------
extern "C" void kernel_launch(void* const* d_in, const int* in_sizes, int n_in,
                              void* d_out, int out_size) {
    const int*   cont_ids   = (const int*)  d_in[0];
    const float* cont_vals  = (const float*)d_in[1];
    const int*   cont_days  = (const int*)  d_in[2];
    const int*   categ_ids  = (const int*)  d_in[3];
    const int*   categ_voc  = (const int*)  d_in[4];
    const int*   categ_days = (const int*)  d_in[5];
    const float* ea_table   = (const float*)d_in[6];
    const float* categ_tab  = (const float*)d_in[7];

    const int n = in_sizes[0];

    float* out       = (float*)d_out;
    float* out_categ = out + (long long)n * D_CONT;

    // PE tables (fp32), integer range reduction; regenerated every call.
    k_theta<<<1, 256>>>();
    {
        int total = MAXDAY * 129;
        k_pe<<<(total + 255) / 256, 256>>>();
    }

    int blocks = (n + 7) / 8;
    k_cont<<<blocks, 256>>>(cont_ids, cont_vals, cont_days, ea_table, out, n);

    bool aligned = ((((long long)n * D_CONT) & 3) == 0) &&
                   ((((unsigned long long)(size_t)out_categ) & 15ULL) == 0ULL);
    if (aligned) {
        k_categ<<<blocks, 256>>>(categ_ids, categ_voc, categ_days,
                                 (const float4*)ea_table,
                                 (const float4*)categ_tab,
                                 (float4*)out_categ, n);
    } else {
        k_categ_scalar<<<blocks, 256>>>(categ_ids, categ_voc, categ_days,
                                        ea_table, categ_tab, out_categ, n);
    }
}

// round 5
// speedup vs baseline: 1.2420x; 1.0261x over previous
#include <cuda_runtime.h>
#include <cuda_fp16.h>
#include <cstdint>

// ---------------------------------------------------------------------------
// Problem constants
// ---------------------------------------------------------------------------
#define N_TABLES 64
#define VOCAB    1024
#define D_EA     128
#define D_CONT   129
#define MAXDAY   3650
#define P129H    132          // half stride for pe129 rows: 264B, 8B-aligned

// ---------------------------------------------------------------------------
// Scratch (device globals; no allocation allowed)
// ---------------------------------------------------------------------------
// theta_q[p]: per-day angle increment in units of 2^-32 turns (fixed point).
// p in [0,65)   -> pe129 pairs (j = p),      d = 129
// p in [65,129) -> pe128 pairs (j = p - 65), d = 128
__device__ unsigned int g_theta_q[129];
__device__ __align__(16) __half g_pe129h[MAXDAY * P129H];   // ~0.96 MB
__device__ __align__(16) __half g_pe128h[MAXDAY * D_EA];    // ~0.93 MB

// ---------------------------------------------------------------------------
// Stage 1: fixed-point angle increments (double pow runs only 129 times).
// ---------------------------------------------------------------------------
__global__ void k_theta() {
    int p = threadIdx.x;
    if (p >= 129) return;
    bool is129 = p < 65;
    int j = is129 ? p : p - 65;
    int d = is129 ? D_CONT : D_EA;
    const double INV_TWO_PI = 0.15915494309189533576888376337251;
    double invdiv = pow(10000.0, -(double)(2 * j) / (double)d);
    double turns  = invdiv * INV_TWO_PI;
    double frac   = turns - floor(turns);
    unsigned long long q = (unsigned long long)(frac * 4294967296.0 + 0.5);
    g_theta_q[p] = (unsigned int)q;
}

// ---------------------------------------------------------------------------
// Stage 2: PE tables (fp16), integer range reduction.
// q = day * theta_q wraps mod 2^32 == exact mod 2*pi; signed reinterpret
// gives turns in [-0.5, 0.5); sincosf on |f| <= pi.
// ---------------------------------------------------------------------------
__global__ void k_pe() {
    int tid = blockIdx.x * blockDim.x + threadIdx.x;
    const int PAIRS = 129;
    if (tid >= MAXDAY * PAIRS) return;
    int day  = tid / PAIRS;
    int pair = tid - day * PAIRS;

    unsigned int q = (unsigned int)day * g_theta_q[pair];
    const float SCALE = 1.46291807926715968e-09f;   // 2*pi / 2^32
    float f = (float)(int)q * SCALE;
    float s, c;
    sincosf(f, &s, &c);

    if (pair < 65) {
        int j = pair;
        if (j == 64) {
            g_pe129h[day * P129H + 128] = __float2half(s);   // k=128 even -> sin
        } else {
            *reinterpret_cast<__half2*>(&g_pe129h[day * P129H + 2 * j]) =
                __floats2half2_rn(s, c);
        }
    } else {
        int j = pair - 65;
        *reinterpret_cast<__half2*>(&g_pe128h[day * D_EA + 2 * j]) =
            __floats2half2_rn(s, c);
    }
}

// ---------------------------------------------------------------------------
// Fused main kernel: one warp per node; warps [0,n) do the continuous
// branch, warps [n,2n) the categorical branch (divergence is warp-level).
// ---------------------------------------------------------------------------
__global__ void k_main(const int* __restrict__ cont_ids,
                       const float* __restrict__ cont_vals,
                       const int* __restrict__ cont_days,
                       const int* __restrict__ categ_ids,
                       const int* __restrict__ categ_voc,
                       const int* __restrict__ categ_days,
                       const float* __restrict__ ea,
                       const float4* __restrict__ tab4,
                       float* __restrict__ out,
                       float4* __restrict__ out_categ4,
                       int n) {
    int gw   = (blockIdx.x * blockDim.x + threadIdx.x) >> 5;
    int lane = threadIdx.x & 31;

    if (gw < n) {
        // ---- continuous branch ----
        int w   = gw;
        int id  = __ldg(cont_ids  + w);
        int day = __ldg(cont_days + w);
        const float*  earow = ea + id * D_EA;
        const __half* perow = g_pe129h + day * P129H;
        float* o = out + (long long)w * D_CONT;
#pragma unroll
        for (int j = 0; j < 4; j++) {
            int k = lane + 32 * j;
            o[k] = __ldg(earow + k) + __half2float(perow[k]);
        }
        if (lane == 0) o[D_EA] = __ldg(cont_vals + w) + __half2float(perow[D_EA]);
    } else {
        int w = gw - n;
        if (w >= n) return;
        // ---- categorical branch (float4 end-to-end) ----
        int id  = __ldg(categ_ids  + w);
        int v   = __ldg(categ_voc  + w);
        int day = __ldg(categ_days + w);

        const float4* ea4 = reinterpret_cast<const float4*>(ea);
        float4 a = __ldg(ea4 + id * 32 + lane);
        float4 b = __ldg(tab4 + ((long long)id * VOCAB + v) * 32 + lane);

        uint2 pbits = *(reinterpret_cast<const uint2*>(g_pe128h) + day * 32 + lane);
        __half2 p01 = *reinterpret_cast<__half2*>(&pbits.x);
        __half2 p23 = *reinterpret_cast<__half2*>(&pbits.y);
        float2 f01 = __half22float2(p01);
        float2 f23 = __half22float2(p23);

        float4 r;
        r.x = a.x + b.x + f01.x;
        r.y = a.y + b.y + f01.y;
        r.z = a.z + b.z + f23.x;
        r.w = a.w + b.w + f23.y;
        out_categ4[(long long)w * 32 + lane] = r;
    }
}

// ---------------------------------------------------------------------------
// Scalar fallback kernels (used only if categ output offset is misaligned).
// ---------------------------------------------------------------------------
__global__ void k_cont(const int* __restrict__ ids,
                       const float* __restrict__ vals,
                       const int* __restrict__ days,
                       const float* __restrict__ ea,
                       float* __restrict__ out, int n) {
    int w    = (blockIdx.x * blockDim.x + threadIdx.x) >> 5;
    int lane = threadIdx.x & 31;
    if (w >= n) return;
    int id  = __ldg(ids  + w);
    int day = __ldg(days + w);
    const float*  earow = ea + id * D_EA;
    const __half* perow = g_pe129h + day * P129H;
    float* o = out + (long long)w * D_CONT;
#pragma unroll
    for (int j = 0; j < 4; j++) {
        int k = lane + 32 * j;
        o[k] = __ldg(earow + k) + __half2float(perow[k]);
    }
    if (lane == 0) o[D_EA] = __ldg(vals + w) + __half2float(perow[D_EA]);
}

__global__ void k_categ_scalar(const int* __restrict__ ids,
                               const int* __restrict__ vocab,
                               const int* __restrict__ days,
                               const float* __restrict__ ea,
                               const float* __restrict__ tab,
                               float* __restrict__ out, int n) {
    int w    = (blockIdx.x * blockDim.x + threadIdx.x) >> 5;
    int lane = threadIdx.x & 31;
    if (w >= n) return;
    int id  = __ldg(ids   + w);
    int v   = __ldg(vocab + w);
    int day = __ldg(days  + w);
    const float*  earow = ea + id * D_EA;
    const float*  trow  = tab + ((long long)id * VOCAB + v) * D_EA;
    const __half* perow = g_pe128h + day * D_EA;
    float* o = out + (long long)w * D_EA;
#pragma unroll
    for (int j = 0; j < 4; j++) {
        int k = lane + 32 * j;
        o[k] = __ldg(earow + k) + __ldg(trow + k) + __half2float(perow[k]);
    }
}

// ---------------------------------------------------------------------------
// Launch
// ---------------------------------------------------------------------------
extern "C" void kernel_launch(void* const* d_in, const int* in_sizes, int n_in,
                              void* d_out, int out_size) {
    const int*   cont_ids   = (const int*)  d_in[0];
    const float* cont_vals  = (const float*)d_in[1];
    const int*   cont_days  = (const int*)  d_in[2];
    const int*   categ_ids  = (const int*)  d_in[3];
    const int*   categ_voc  = (const int*)  d_in[4];
    const int*   categ_days = (const int*)  d_in[5];
    const float* ea_table   = (const float*)d_in[6];
    const float* categ_tab  = (const float*)d_in[7];

    const int n = in_sizes[0];

    float* out       = (float*)d_out;
    float* out_categ = out + (long long)n * D_CONT;

    // PE tables (fp16), regenerated every call (deterministic, ~7us).
    k_theta<<<1, 256>>>();
    {
        int total = MAXDAY * 129;
        k_pe<<<(total + 255) / 256, 256>>>();
    }

    bool aligned = ((((long long)n * D_CONT) & 3) == 0) &&
                   ((((unsigned long long)(size_t)out_categ) & 15ULL) == 0ULL);
    if (aligned) {
        long long warps = 2LL * n;
        int blocks = (int)((warps + 7) / 8);
        k_main<<<blocks, 256>>>(cont_ids, cont_vals, cont_days,
                                categ_ids, categ_voc, categ_days,
                                ea_table, (const float4*)categ_tab,
                                out, (float4*)out_categ, n);
    } else {
        int blocks = (n + 7) / 8;
        k_cont<<<blocks, 256>>>(cont_ids, cont_vals, cont_days, ea_table, out, n);
        k_categ_scalar<<<blocks, 256>>>(categ_ids, categ_voc, categ_days,
                                        ea_table, categ_tab, out_categ, n);
    }
}

// round 6
// speedup vs baseline: 1.5051x; 1.2119x over previous
#include <cuda_runtime.h>
#include <cuda_fp16.h>
#include <cstdint>

// ---------------------------------------------------------------------------
// Problem constants
// ---------------------------------------------------------------------------
#define N_TABLES 64
#define VOCAB    1024
#define D_EA     128
#define D_CONT   129
#define MAXDAY   3650
#define P129H    132          // half stride for pe129 rows: 264B, 8B-aligned
#define ILP      4            // nodes per warp

// ---------------------------------------------------------------------------
// Scratch (device globals; no allocation allowed)
// ---------------------------------------------------------------------------
__device__ unsigned int g_theta_q[129];
__device__ __align__(16) __half g_pe129h[MAXDAY * P129H];   // ~0.96 MB
__device__ __align__(16) __half g_pe128h[MAXDAY * D_EA];    // ~0.93 MB

// ---------------------------------------------------------------------------
// Stage 1: fixed-point angle increments (double pow runs only 129 times).
// ---------------------------------------------------------------------------
__global__ void k_theta() {
    int p = threadIdx.x;
    if (p >= 129) return;
    bool is129 = p < 65;
    int j = is129 ? p : p - 65;
    int d = is129 ? D_CONT : D_EA;
    const double INV_TWO_PI = 0.15915494309189533576888376337251;
    double invdiv = pow(10000.0, -(double)(2 * j) / (double)d);
    double turns  = invdiv * INV_TWO_PI;
    double frac   = turns - floor(turns);
    unsigned long long q = (unsigned long long)(frac * 4294967296.0 + 0.5);
    g_theta_q[p] = (unsigned int)q;
}

// ---------------------------------------------------------------------------
// Stage 2: PE tables (fp16), integer range reduction.
// ---------------------------------------------------------------------------
__global__ void k_pe() {
    int tid = blockIdx.x * blockDim.x + threadIdx.x;
    const int PAIRS = 129;
    if (tid >= MAXDAY * PAIRS) return;
    int day  = tid / PAIRS;
    int pair = tid - day * PAIRS;

    unsigned int q = (unsigned int)day * g_theta_q[pair];
    const float SCALE = 1.46291807926715968e-09f;   // 2*pi / 2^32
    float f = (float)(int)q * SCALE;
    float s, c;
    sincosf(f, &s, &c);

    if (pair < 65) {
        int j = pair;
        if (j == 64) {
            g_pe129h[day * P129H + 128] = __float2half(s);
        } else {
            *reinterpret_cast<__half2*>(&g_pe129h[day * P129H + 2 * j]) =
                __floats2half2_rn(s, c);
        }
    } else {
        int j = pair - 65;
        *reinterpret_cast<__half2*>(&g_pe128h[day * D_EA + 2 * j]) =
            __floats2half2_rn(s, c);
    }
}

// ---------------------------------------------------------------------------
// Fused main kernel, ILP=4 nodes per warp, front-batched loads.
// Warp-groups [0, ngrp) -> continuous nodes, [ngrp, 2*ngrp) -> categorical.
// ---------------------------------------------------------------------------
__global__ __launch_bounds__(256, 4)
void k_main(const int* __restrict__ cont_ids,
            const float* __restrict__ cont_vals,
            const int* __restrict__ cont_days,
            const int* __restrict__ categ_ids,
            const int* __restrict__ categ_voc,
            const int* __restrict__ categ_days,
            const float* __restrict__ ea,
            const float4* __restrict__ tab4,
            float* __restrict__ out,
            float4* __restrict__ out_categ4,
            int n) {
    int gw   = (blockIdx.x * blockDim.x + threadIdx.x) >> 5;
    int lane = threadIdx.x & 31;
    int ngrp = (n + ILP - 1) / ILP;

    if (gw < ngrp) {
        // ---------------- continuous branch ----------------
        int base = gw * ILP;
        int cnt  = n - base; if (cnt > ILP) cnt = ILP;

        int id[ILP], day[ILP];
#pragma unroll
        for (int m = 0; m < ILP; m++) {
            int w = (m < cnt) ? base + m : base;
            id[m]  = __ldg(cont_ids  + w);
            day[m] = __ldg(cont_days + w);
        }

        float  ev[ILP][4];
        __half pv[ILP][4];
#pragma unroll
        for (int m = 0; m < ILP; m++) {
            const float*  earow = ea + id[m] * D_EA;
            const __half* perow = g_pe129h + day[m] * P129H;
#pragma unroll
            for (int j = 0; j < 4; j++) {
                int k = lane + 32 * j;
                ev[m][j] = __ldg(earow + k);
                pv[m][j] = perow[k];
            }
        }
        float edge[ILP];
#pragma unroll
        for (int m = 0; m < ILP; m++) {
            int w = (m < cnt) ? base + m : base;
            if (lane == 0)
                edge[m] = __ldg(cont_vals + w) +
                          __half2float(g_pe129h[day[m] * P129H + D_EA]);
        }
#pragma unroll
        for (int m = 0; m < ILP; m++) {
            if (m >= cnt) break;
            float* o = out + (long long)(base + m) * D_CONT;
#pragma unroll
            for (int j = 0; j < 4; j++) {
                int k = lane + 32 * j;
                o[k] = ev[m][j] + __half2float(pv[m][j]);
            }
            if (lane == 0) o[D_EA] = edge[m];
        }
    } else {
        // ---------------- categorical branch ----------------
        int g = gw - ngrp;
        if (g >= ngrp) return;
        int base = g * ILP;
        int cnt  = n - base; if (cnt > ILP) cnt = ILP;

        int id[ILP], v[ILP], day[ILP];
#pragma unroll
        for (int m = 0; m < ILP; m++) {
            int w = (m < cnt) ? base + m : base;
            id[m]  = __ldg(categ_ids  + w);
            v[m]   = __ldg(categ_voc  + w);
            day[m] = __ldg(categ_days + w);
        }

        const float4* ea4 = reinterpret_cast<const float4*>(ea);
        float4 a[ILP], b[ILP];
        uint2  p[ILP];
#pragma unroll
        for (int m = 0; m < ILP; m++) {
            a[m] = __ldg(ea4 + id[m] * 32 + lane);
            b[m] = __ldg(tab4 + ((long long)id[m] * VOCAB + v[m]) * 32 + lane);
            p[m] = *(reinterpret_cast<const uint2*>(g_pe128h) + day[m] * 32 + lane);
        }
#pragma unroll
        for (int m = 0; m < ILP; m++) {
            if (m >= cnt) break;
            __half2 p01 = *reinterpret_cast<__half2*>(&p[m].x);
            __half2 p23 = *reinterpret_cast<__half2*>(&p[m].y);
            float2 f01 = __half22float2(p01);
            float2 f23 = __half22float2(p23);
            float4 r;
            r.x = a[m].x + b[m].x + f01.x;
            r.y = a[m].y + b[m].y + f01.y;
            r.z = a[m].z + b[m].z + f23.x;
            r.w = a[m].w + b[m].w + f23.y;
            out_categ4[(long long)(base + m) * 32 + lane] = r;
        }
    }
}

// ---------------------------------------------------------------------------
// Scalar fallback kernels (used only if categ output offset is misaligned).
// ---------------------------------------------------------------------------
__global__ void k_cont(const int* __restrict__ ids,
                       const float* __restrict__ vals,
                       const int* __restrict__ days,
                       const float* __restrict__ ea,
                       float* __restrict__ out, int n) {
    int w    = (blockIdx.x * blockDim.x + threadIdx.x) >> 5;
    int lane = threadIdx.x & 31;
    if (w >= n) return;
    int id  = __ldg(ids  + w);
    int day = __ldg(days + w);
    const float*  earow = ea + id * D_EA;
    const __half* perow = g_pe129h + day * P129H;
    float* o = out + (long long)w * D_CONT;
#pragma unroll
    for (int j = 0; j < 4; j++) {
        int k = lane + 32 * j;
        o[k] = __ldg(earow + k) + __half2float(perow[k]);
    }
    if (lane == 0) o[D_EA] = __ldg(vals + w) + __half2float(perow[D_EA]);
}

__global__ void k_categ_scalar(const int* __restrict__ ids,
                               const int* __restrict__ vocab,
                               const int* __restrict__ days,
                               const float* __restrict__ ea,
                               const float* __restrict__ tab,
                               float* __restrict__ out, int n) {
    int w    = (blockIdx.x * blockDim.x + threadIdx.x) >> 5;
    int lane = threadIdx.x & 31;
    if (w >= n) return;
    int id  = __ldg(ids   + w);
    int v   = __ldg(vocab + w);
    int day = __ldg(days  + w);
    const float*  earow = ea + id * D_EA;
    const float*  trow  = tab + ((long long)id * VOCAB + v) * D_EA;
    const __half* perow = g_pe128h + day * D_EA;
    float* o = out + (long long)w * D_EA;
#pragma unroll
    for (int j = 0; j < 4; j++) {
        int k = lane + 32 * j;
        o[k] = __ldg(earow + k) + __ldg(trow + k) + __half2float(perow[k]);
    }
}

// ---------------------------------------------------------------------------
// Launch
// ---------------------------------------------------------------------------
extern "C" void kernel_launch(void* const* d_in, const int* in_sizes, int n_in,
                              void* d_out, int out_size) {
    const int*   cont_ids   = (const int*)  d_in[0];
    const float* cont_vals  = (const float*)d_in[1];
    const int*   cont_days  = (const int*)  d_in[2];
    const int*   categ_ids  = (const int*)  d_in[3];
    const int*   categ_voc  = (const int*)  d_in[4];
    const int*   categ_days = (const int*)  d_in[5];
    const float* ea_table   = (const float*)d_in[6];
    const float* categ_tab  = (const float*)d_in[7];

    const int n = in_sizes[0];

    float* out       = (float*)d_out;
    float* out_categ = out + (long long)n * D_CONT;

    // PE tables (fp16), regenerated every call (deterministic, ~15us).
    k_theta<<<1, 256>>>();
    {
        int total = MAXDAY * 129;
        k_pe<<<(total + 255) / 256, 256>>>();
    }

    bool aligned = ((((long long)n * D_CONT) & 3) == 0) &&
                   ((((unsigned long long)(size_t)out_categ) & 15ULL) == 0ULL);
    if (aligned) {
        long long ngrp  = (n + ILP - 1) / ILP;
        long long warps = 2LL * ngrp;
        int blocks = (int)((warps + 7) / 8);
        k_main<<<blocks, 256>>>(cont_ids, cont_vals, cont_days,
                                categ_ids, categ_voc, categ_days,
                                ea_table, (const float4*)categ_tab,
                                out, (float4*)out_categ, n);
    } else {
        int blocks = (n + 7) / 8;
        k_cont<<<blocks, 256>>>(cont_ids, cont_vals, cont_days, ea_table, out, n);
        k_categ_scalar<<<blocks, 256>>>(categ_ids, categ_voc, categ_days,
                                        ea_table, categ_tab, out_categ, n);
    }
}

// round 7
// speedup vs baseline: 1.5072x; 1.0014x over previous
#include <cuda_runtime.h>
#include <cuda_fp16.h>
#include <cstdint>

// ---------------------------------------------------------------------------
// Problem constants
// ---------------------------------------------------------------------------
#define N_TABLES 64
#define VOCAB    1024
#define D_EA     128
#define D_CONT   129
#define MAXDAY   3650
#define P129H    132          // half stride for pe129 rows: 264B, 8B-aligned
#define ILP      4            // nodes per warp

// ---------------------------------------------------------------------------
// Scratch (device globals; no allocation allowed)
// ---------------------------------------------------------------------------
__device__ __align__(16) __half g_pe129h[MAXDAY * P129H];   // ~0.96 MB
__device__ __align__(16) __half g_pe128h[MAXDAY * D_EA];    // ~0.93 MB

// ---------------------------------------------------------------------------
// PE table generation, one (dim-pair) per block. Thread 0 computes the
// fixed-point per-day angle increment (the ONLY double pow, 129 total,
// paid in parallel across blocks); 256 threads then sweep 3650 days.
// q = day * theta wraps mod 2^32 == exact mod 2*pi; signed reinterpret
// gives turns in [-0.5, 0.5); sincosf on |f| <= pi.
// pair in [0,65)   -> pe129 (j = pair),      d = 129
// pair in [65,129) -> pe128 (j = pair - 65), d = 128
// ---------------------------------------------------------------------------
__global__ void k_pe() {
    __shared__ unsigned int s_theta;
    int pair = blockIdx.x;
    bool is129 = pair < 65;
    int j = is129 ? pair : pair - 65;

    if (threadIdx.x == 0) {
        int d = is129 ? D_CONT : D_EA;
        const double INV_TWO_PI = 0.15915494309189533576888376337251;
        double invdiv = pow(10000.0, -(double)(2 * j) / (double)d);
        double turns  = invdiv * INV_TWO_PI;
        double frac   = turns - floor(turns);
        unsigned long long q64 = (unsigned long long)(frac * 4294967296.0 + 0.5);
        s_theta = (unsigned int)q64;
    }
    __syncthreads();
    unsigned int theta = s_theta;

    const float SCALE = 1.46291807926715968e-09f;   // 2*pi / 2^32
    for (int day = threadIdx.x; day < MAXDAY; day += blockDim.x) {
        unsigned int q = (unsigned int)day * theta;
        float f = (float)(int)q * SCALE;
        float s, c;
        sincosf(f, &s, &c);
        if (is129) {
            if (j == 64) {
                g_pe129h[day * P129H + 128] = __float2half(s);  // k=128 even -> sin
            } else {
                *reinterpret_cast<__half2*>(&g_pe129h[day * P129H + 2 * j]) =
                    __floats2half2_rn(s, c);
            }
        } else {
            *reinterpret_cast<__half2*>(&g_pe128h[day * D_EA + 2 * j]) =
                __floats2half2_rn(s, c);
        }
    }
}

// ---------------------------------------------------------------------------
// Fused main kernel, ILP=4 nodes per warp, front-batched loads (R6 winner,
// unchanged). Warp-groups [0, ngrp) -> continuous, [ngrp, 2*ngrp) -> categ.
// ---------------------------------------------------------------------------
__global__ __launch_bounds__(256, 4)
void k_main(const int* __restrict__ cont_ids,
            const float* __restrict__ cont_vals,
            const int* __restrict__ cont_days,
            const int* __restrict__ categ_ids,
            const int* __restrict__ categ_voc,
            const int* __restrict__ categ_days,
            const float* __restrict__ ea,
            const float4* __restrict__ tab4,
            float* __restrict__ out,
            float4* __restrict__ out_categ4,
            int n) {
    int gw   = (blockIdx.x * blockDim.x + threadIdx.x) >> 5;
    int lane = threadIdx.x & 31;
    int ngrp = (n + ILP - 1) / ILP;

    if (gw < ngrp) {
        // ---------------- continuous branch ----------------
        int base = gw * ILP;
        int cnt  = n - base; if (cnt > ILP) cnt = ILP;

        int id[ILP], day[ILP];
#pragma unroll
        for (int m = 0; m < ILP; m++) {
            int w = (m < cnt) ? base + m : base;
            id[m]  = __ldg(cont_ids  + w);
            day[m] = __ldg(cont_days + w);
        }

        float  ev[ILP][4];
        __half pv[ILP][4];
#pragma unroll
        for (int m = 0; m < ILP; m++) {
            const float*  earow = ea + id[m] * D_EA;
            const __half* perow = g_pe129h + day[m] * P129H;
#pragma unroll
            for (int j = 0; j < 4; j++) {
                int k = lane + 32 * j;
                ev[m][j] = __ldg(earow + k);
                pv[m][j] = perow[k];
            }
        }
        float edge[ILP];
#pragma unroll
        for (int m = 0; m < ILP; m++) {
            int w = (m < cnt) ? base + m : base;
            if (lane == 0)
                edge[m] = __ldg(cont_vals + w) +
                          __half2float(g_pe129h[day[m] * P129H + D_EA]);
        }
#pragma unroll
        for (int m = 0; m < ILP; m++) {
            if (m >= cnt) break;
            float* o = out + (long long)(base + m) * D_CONT;
#pragma unroll
            for (int j = 0; j < 4; j++) {
                int k = lane + 32 * j;
                o[k] = ev[m][j] + __half2float(pv[m][j]);
            }
            if (lane == 0) o[D_EA] = edge[m];
        }
    } else {
        // ---------------- categorical branch ----------------
        int g = gw - ngrp;
        if (g >= ngrp) return;
        int base = g * ILP;
        int cnt  = n - base; if (cnt > ILP) cnt = ILP;

        int id[ILP], v[ILP], day[ILP];
#pragma unroll
        for (int m = 0; m < ILP; m++) {
            int w = (m < cnt) ? base + m : base;
            id[m]  = __ldg(categ_ids  + w);
            v[m]   = __ldg(categ_voc  + w);
            day[m] = __ldg(categ_days + w);
        }

        const float4* ea4 = reinterpret_cast<const float4*>(ea);
        float4 a[ILP], b[ILP];
        uint2  p[ILP];
#pragma unroll
        for (int m = 0; m < ILP; m++) {
            a[m] = __ldg(ea4 + id[m] * 32 + lane);
            b[m] = __ldg(tab4 + ((long long)id[m] * VOCAB + v[m]) * 32 + lane);
            p[m] = *(reinterpret_cast<const uint2*>(g_pe128h) + day[m] * 32 + lane);
        }
#pragma unroll
        for (int m = 0; m < ILP; m++) {
            if (m >= cnt) break;
            __half2 p01 = *reinterpret_cast<__half2*>(&p[m].x);
            __half2 p23 = *reinterpret_cast<__half2*>(&p[m].y);
            float2 f01 = __half22float2(p01);
            float2 f23 = __half22float2(p23);
            float4 r;
            r.x = a[m].x + b[m].x + f01.x;
            r.y = a[m].y + b[m].y + f01.y;
            r.z = a[m].z + b[m].z + f23.x;
            r.w = a[m].w + b[m].w + f23.y;
            out_categ4[(long long)(base + m) * 32 + lane] = r;
        }
    }
}

// ---------------------------------------------------------------------------
// Scalar fallback kernels (used only if categ output offset is misaligned).
// ---------------------------------------------------------------------------
__global__ void k_cont(const int* __restrict__ ids,
                       const float* __restrict__ vals,
                       const int* __restrict__ days,
                       const float* __restrict__ ea,
                       float* __restrict__ out, int n) {
    int w    = (blockIdx.x * blockDim.x + threadIdx.x) >> 5;
    int lane = threadIdx.x & 31;
    if (w >= n) return;
    int id  = __ldg(ids  + w);
    int day = __ldg(days + w);
    const float*  earow = ea + id * D_EA;
    const __half* perow = g_pe129h + day * P129H;
    float* o = out + (long long)w * D_CONT;
#pragma unroll
    for (int j = 0; j < 4; j++) {
        int k = lane + 32 * j;
        o[k] = __ldg(earow + k) + __half2float(perow[k]);
    }
    if (lane == 0) o[D_EA] = __ldg(vals + w) + __half2float(perow[D_EA]);
}

__global__ void k_categ_scalar(const int* __restrict__ ids,
                               const int* __restrict__ vocab,
                               const int* __restrict__ days,
                               const float* __restrict__ ea,
                               const float* __restrict__ tab,
                               float* __restrict__ out, int n) {
    int w    = (blockIdx.x * blockDim.x + threadIdx.x) >> 5;
    int lane = threadIdx.x & 31;
    if (w >= n) return;
    int id  = __ldg(ids   + w);
    int v   = __ldg(vocab + w);
    int day = __ldg(days  + w);
    const float*  earow = ea + id * D_EA;
    const float*  trow  = tab + ((long long)id * VOCAB + v) * D_EA;
    const __half* perow = g_pe128h + day * D_EA;
    float* o = out + (long long)w * D_EA;
#pragma unroll
    for (int j = 0; j < 4; j++) {
        int k = lane + 32 * j;
        o[k] = __ldg(earow + k) + __ldg(trow + k) + __half2float(perow[k]);
    }
}

// ---------------------------------------------------------------------------
// Launch
// ---------------------------------------------------------------------------
extern "C" void kernel_launch(void* const* d_in, const int* in_sizes, int n_in,
                              void* d_out, int out_size) {
    const int*   cont_ids   = (const int*)  d_in[0];
    const float* cont_vals  = (const float*)d_in[1];
    const int*   cont_days  = (const int*)  d_in[2];
    const int*   categ_ids  = (const int*)  d_in[3];
    const int*   categ_voc  = (const int*)  d_in[4];
    const int*   categ_days = (const int*)  d_in[5];
    const float* ea_table   = (const float*)d_in[6];
    const float* categ_tab  = (const float*)d_in[7];

    const int n = in_sizes[0];

    float* out       = (float*)d_out;
    float* out_categ = out + (long long)n * D_CONT;

    // PE tables (fp16), single fused kernel: 129 blocks (one per dim-pair).
    k_pe<<<129, 256>>>();

    bool aligned = ((((long long)n * D_CONT) & 3) == 0) &&
                   ((((unsigned long long)(size_t)out_categ) & 15ULL) == 0ULL);
    if (aligned) {
        long long ngrp  = (n + ILP - 1) / ILP;
        long long warps = 2LL * ngrp;
        int blocks = (int)((warps + 7) / 8);
        k_main<<<blocks, 256>>>(cont_ids, cont_vals, cont_days,
                                categ_ids, categ_voc, categ_days,
                                ea_table, (const float4*)categ_tab,
                                out, (float4*)out_categ, n);
    } else {
        int blocks = (n + 7) / 8;
        k_cont<<<blocks, 256>>>(cont_ids, cont_vals, cont_days, ea_table, out, n);
        k_categ_scalar<<<blocks, 256>>>(categ_ids, categ_voc, categ_days,
                                        ea_table, categ_tab, out_categ, n);
    }
}

// round 8
// speedup vs baseline: 1.6069x; 1.0662x over previous
#include <cuda_runtime.h>
#include <cuda_fp16.h>
#include <cstdint>

// ---------------------------------------------------------------------------
// Problem constants
// ---------------------------------------------------------------------------
#define N_TABLES 64
#define VOCAB    1024
#define D_EA     128
#define D_CONT   129
#define MAXDAY   3650
#define P129H    132          // half stride for pe129 rows: 264B, 8B-aligned
#define ILP      4            // nodes per warp

// ---------------------------------------------------------------------------
// Scratch (device globals; no allocation allowed)
// ---------------------------------------------------------------------------
__device__ __align__(16) __half g_pe129h[MAXDAY * P129H];   // ~0.96 MB
__device__ __align__(16) __half g_pe128h[MAXDAY * D_EA];    // ~0.93 MB

// ---------------------------------------------------------------------------
// PE table generation, one dim-pair per block (129 blocks). Thread 0 does
// the only double pow; 256 threads sweep 3650 days with integer
// fixed-point range reduction (q wraps mod 2^32 == exact mod 2*pi).
// ---------------------------------------------------------------------------
__global__ void k_pe() {
    __shared__ unsigned int s_theta;
    int pair = blockIdx.x;
    bool is129 = pair < 65;
    int j = is129 ? pair : pair - 65;

    if (threadIdx.x == 0) {
        int d = is129 ? D_CONT : D_EA;
        const double INV_TWO_PI = 0.15915494309189533576888376337251;
        double invdiv = pow(10000.0, -(double)(2 * j) / (double)d);
        double turns  = invdiv * INV_TWO_PI;
        double frac   = turns - floor(turns);
        unsigned long long q64 = (unsigned long long)(frac * 4294967296.0 + 0.5);
        s_theta = (unsigned int)q64;
    }
    __syncthreads();
    unsigned int theta = s_theta;

    const float SCALE = 1.46291807926715968e-09f;   // 2*pi / 2^32
    for (int day = threadIdx.x; day < MAXDAY; day += blockDim.x) {
        unsigned int q = (unsigned int)day * theta;
        float f = (float)(int)q * SCALE;
        float s, c;
        sincosf(f, &s, &c);
        if (is129) {
            if (j == 64) {
                g_pe129h[day * P129H + 128] = __float2half(s);  // k=128 even -> sin
            } else {
                *reinterpret_cast<__half2*>(&g_pe129h[day * P129H + 2 * j]) =
                    __floats2half2_rn(s, c);
            }
        } else {
            *reinterpret_cast<__half2*>(&g_pe128h[day * D_EA + 2 * j]) =
                __floats2half2_rn(s, c);
        }
    }
}

// ---------------------------------------------------------------------------
// Fused main kernel, ILP=4 nodes per warp. Long-latency loads (categ table
// gather, PE rows: L2 ~250-380cyc) are front-batched; ea-table reads are
// L1-resident (32KB) and issue inside the combine loop. launch_bounds(256,5)
// caps regs at 51 -> up to 40 warps/SM.
// ---------------------------------------------------------------------------
__global__ __launch_bounds__(256, 5)
void k_main(const int* __restrict__ cont_ids,
            const float* __restrict__ cont_vals,
            const int* __restrict__ cont_days,
            const int* __restrict__ categ_ids,
            const int* __restrict__ categ_voc,
            const int* __restrict__ categ_days,
            const float* __restrict__ ea,
            const float4* __restrict__ tab4,
            float* __restrict__ out,
            float4* __restrict__ out_categ4,
            int n) {
    int gw   = (blockIdx.x * blockDim.x + threadIdx.x) >> 5;
    int lane = threadIdx.x & 31;
    int ngrp = (n + ILP - 1) / ILP;

    if (gw < ngrp) {
        // ---------------- continuous branch ----------------
        int base = gw * ILP;
        int cnt  = n - base; if (cnt > ILP) cnt = ILP;

        int id[ILP], day[ILP];
#pragma unroll
        for (int m = 0; m < ILP; m++) {
            int w = (m < cnt) ? base + m : base;
            id[m]  = __ldg(cont_ids  + w);
            day[m] = __ldg(cont_days + w);
        }

        // Front-batch the L2-latency PE reads.
        __half pv[ILP][4];
#pragma unroll
        for (int m = 0; m < ILP; m++) {
            const __half* perow = g_pe129h + day[m] * P129H;
#pragma unroll
            for (int j = 0; j < 4; j++)
                pv[m][j] = perow[lane + 32 * j];
        }
        float edge[ILP];
#pragma unroll
        for (int m = 0; m < ILP; m++) {
            int w = (m < cnt) ? base + m : base;
            if (lane == 0)
                edge[m] = __ldg(cont_vals + w) +
                          __half2float(g_pe129h[day[m] * P129H + D_EA]);
        }
        // ea rows are L1 hits; load inside the combine loop.
#pragma unroll
        for (int m = 0; m < ILP; m++) {
            if (m >= cnt) break;
            const float* earow = ea + id[m] * D_EA;
            float* o = out + (base + m) * D_CONT;
#pragma unroll
            for (int j = 0; j < 4; j++) {
                int k = lane + 32 * j;
                o[k] = __ldg(earow + k) + __half2float(pv[m][j]);
            }
            if (lane == 0) o[D_EA] = edge[m];
        }
    } else {
        // ---------------- categorical branch ----------------
        int g = gw - ngrp;
        if (g >= ngrp) return;
        int base = g * ILP;
        int cnt  = n - base; if (cnt > ILP) cnt = ILP;

        int id[ILP], v[ILP], day[ILP];
#pragma unroll
        for (int m = 0; m < ILP; m++) {
            int w = (m < cnt) ? base + m : base;
            id[m]  = __ldg(categ_ids  + w);
            v[m]   = __ldg(categ_voc  + w);
            day[m] = __ldg(categ_days + w);
        }

        // Front-batch the long-latency loads: table gather + PE rows.
        float4 b[ILP];
        uint2  p[ILP];
#pragma unroll
        for (int m = 0; m < ILP; m++) {
            b[m] = __ldg(tab4 + (id[m] * VOCAB + v[m]) * 32 + lane);
            p[m] = *(reinterpret_cast<const uint2*>(g_pe128h) + day[m] * 32 + lane);
        }
        // ea rows are L1 hits; load inside the combine loop.
        const float4* ea4 = reinterpret_cast<const float4*>(ea);
#pragma unroll
        for (int m = 0; m < ILP; m++) {
            if (m >= cnt) break;
            float4 a = __ldg(ea4 + id[m] * 32 + lane);
            __half2 p01 = *reinterpret_cast<__half2*>(&p[m].x);
            __half2 p23 = *reinterpret_cast<__half2*>(&p[m].y);
            float2 f01 = __half22float2(p01);
            float2 f23 = __half22float2(p23);
            float4 r;
            r.x = a.x + b[m].x + f01.x;
            r.y = a.y + b[m].y + f01.y;
            r.z = a.z + b[m].z + f23.x;
            r.w = a.w + b[m].w + f23.y;
            out_categ4[(base + m) * 32 + lane] = r;
        }
    }
}

// ---------------------------------------------------------------------------
// Scalar fallback kernels (used only if categ output offset is misaligned).
// ---------------------------------------------------------------------------
__global__ void k_cont(const int* __restrict__ ids,
                       const float* __restrict__ vals,
                       const int* __restrict__ days,
                       const float* __restrict__ ea,
                       float* __restrict__ out, int n) {
    int w    = (blockIdx.x * blockDim.x + threadIdx.x) >> 5;
    int lane = threadIdx.x & 31;
    if (w >= n) return;
    int id  = __ldg(ids  + w);
    int day = __ldg(days + w);
    const float*  earow = ea + id * D_EA;
    const __half* perow = g_pe129h + day * P129H;
    float* o = out + (long long)w * D_CONT;
#pragma unroll
    for (int j = 0; j < 4; j++) {
        int k = lane + 32 * j;
        o[k] = __ldg(earow + k) + __half2float(perow[k]);
    }
    if (lane == 0) o[D_EA] = __ldg(vals + w) + __half2float(perow[D_EA]);
}

__global__ void k_categ_scalar(const int* __restrict__ ids,
                               const int* __restrict__ vocab,
                               const int* __restrict__ days,
                               const float* __restrict__ ea,
                               const float* __restrict__ tab,
                               float* __restrict__ out, int n) {
    int w    = (blockIdx.x * blockDim.x + threadIdx.x) >> 5;
    int lane = threadIdx.x & 31;
    if (w >= n) return;
    int id  = __ldg(ids   + w);
    int v   = __ldg(vocab + w);
    int day = __ldg(days  + w);
    const float*  earow = ea + id * D_EA;
    const float*  trow  = tab + ((long long)id * VOCAB + v) * D_EA;
    const __half* perow = g_pe128h + day * D_EA;
    float* o = out + (long long)w * D_EA;
#pragma unroll
    for (int j = 0; j < 4; j++) {
        int k = lane + 32 * j;
        o[k] = __ldg(earow + k) + __ldg(trow + k) + __half2float(perow[k]);
    }
}

// ---------------------------------------------------------------------------
// Launch
// ---------------------------------------------------------------------------
extern "C" void kernel_launch(void* const* d_in, const int* in_sizes, int n_in,
                              void* d_out, int out_size) {
    const int*   cont_ids   = (const int*)  d_in[0];
    const float* cont_vals  = (const float*)d_in[1];
    const int*   cont_days  = (const int*)  d_in[2];
    const int*   categ_ids  = (const int*)  d_in[3];
    const int*   categ_voc  = (const int*)  d_in[4];
    const int*   categ_days = (const int*)  d_in[5];
    const float* ea_table   = (const float*)d_in[6];
    const float* categ_tab  = (const float*)d_in[7];

    const int n = in_sizes[0];

    float* out       = (float*)d_out;
    float* out_categ = out + (long long)n * D_CONT;

    // PE tables (fp16), single fused kernel: 129 blocks (one per dim-pair).
    k_pe<<<129, 256>>>();

    bool aligned = ((((long long)n * D_CONT) & 3) == 0) &&
                   ((((unsigned long long)(size_t)out_categ) & 15ULL) == 0ULL);
    if (aligned) {
        long long ngrp  = (n + ILP - 1) / ILP;
        long long warps = 2LL * ngrp;
        int blocks = (int)((warps + 7) / 8);
        k_main<<<blocks, 256>>>(cont_ids, cont_vals, cont_days,
                                categ_ids, categ_voc, categ_days,
                                ea_table, (const float4*)categ_tab,
                                out, (float4*)out_categ, n);
    } else {
        int blocks = (n + 7) / 8;
        k_cont<<<blocks, 256>>>(cont_ids, cont_vals, cont_days, ea_table, out, n);
        k_categ_scalar<<<blocks, 256>>>(categ_ids, categ_voc, categ_days,
                                        ea_table, categ_tab, out_categ, n);
    }
}

// round 9
// speedup vs baseline: 1.9488x; 1.2128x over previous
#include <cuda_runtime.h>
#include <cuda_fp16.h>
#include <cstdint>

// ---------------------------------------------------------------------------
// Problem constants
// ---------------------------------------------------------------------------
#define N_TABLES 64
#define VOCAB    1024
#define D_EA     128
#define D_CONT   129
#define MAXDAY   3650
#define P129H    132          // half stride for pe129 rows: 264B, 8B-aligned
#define ILP      4            // nodes per warp

// ---------------------------------------------------------------------------
// Scratch (device globals; no allocation allowed)
// ---------------------------------------------------------------------------
__device__ __align__(16) __half g_pe129h[MAXDAY * P129H];   // ~0.96 MB
__device__ __align__(16) __half g_pe128h[MAXDAY * D_EA];    // ~0.93 MB

// ---------------------------------------------------------------------------
// PE table generation, one dim-pair per block (129 blocks). Thread 0 does
// the only double pow; 256 threads sweep 3650 days with integer
// fixed-point range reduction (q wraps mod 2^32 == exact mod 2*pi).
// ---------------------------------------------------------------------------
__global__ void k_pe() {
    __shared__ unsigned int s_theta;
    int pair = blockIdx.x;
    bool is129 = pair < 65;
    int j = is129 ? pair : pair - 65;

    if (threadIdx.x == 0) {
        int d = is129 ? D_CONT : D_EA;
        const double INV_TWO_PI = 0.15915494309189533576888376337251;
        double invdiv = pow(10000.0, -(double)(2 * j) / (double)d);
        double turns  = invdiv * INV_TWO_PI;
        double frac   = turns - floor(turns);
        unsigned long long q64 = (unsigned long long)(frac * 4294967296.0 + 0.5);
        s_theta = (unsigned int)q64;
    }
    __syncthreads();
    unsigned int theta = s_theta;

    const float SCALE = 1.46291807926715968e-09f;   // 2*pi / 2^32
    for (int day = threadIdx.x; day < MAXDAY; day += blockDim.x) {
        unsigned int q = (unsigned int)day * theta;
        float f = (float)(int)q * SCALE;
        float s, c;
        sincosf(f, &s, &c);
        if (is129) {
            if (j == 64) {
                g_pe129h[day * P129H + 128] = __float2half(s);  // k=128 even -> sin
            } else {
                *reinterpret_cast<__half2*>(&g_pe129h[day * P129H + 2 * j]) =
                    __floats2half2_rn(s, c);
            }
        } else {
            *reinterpret_cast<__half2*>(&g_pe128h[day * D_EA + 2 * j]) =
                __floats2half2_rn(s, c);
        }
    }
}

// ---------------------------------------------------------------------------
// Fused main kernel, FULL variant: requires n % ILP == 0 (no tail logic).
// ILP=4 nodes per warp, long-latency loads front-batched, ea rows (L1-
// resident 32KB) loaded in the combine loop. launch_bounds(256,6) -> regs
// capped at 42 -> up to 48 warps/SM.
// ---------------------------------------------------------------------------
__global__ __launch_bounds__(256, 6)
void k_main_full(const int* __restrict__ cont_ids,
                 const float* __restrict__ cont_vals,
                 const int* __restrict__ cont_days,
                 const int* __restrict__ categ_ids,
                 const int* __restrict__ categ_voc,
                 const int* __restrict__ categ_days,
                 const float* __restrict__ ea,
                 const float4* __restrict__ tab4,
                 float* __restrict__ out,
                 float4* __restrict__ out_categ4,
                 int n) {
    int gw   = (blockIdx.x * blockDim.x + threadIdx.x) >> 5;
    int lane = threadIdx.x & 31;
    int ngrp = n / ILP;

    if (gw < ngrp) {
        // ---------------- continuous branch ----------------
        int base = gw * ILP;

        int id[ILP], day[ILP];
#pragma unroll
        for (int m = 0; m < ILP; m++) {
            id[m]  = __ldg(cont_ids  + base + m);
            day[m] = __ldg(cont_days + base + m);
        }

        // Front-batch the L2-latency PE reads.
        __half pv[ILP][4];
#pragma unroll
        for (int m = 0; m < ILP; m++) {
            const __half* perow = g_pe129h + day[m] * P129H;
#pragma unroll
            for (int j = 0; j < 4; j++)
                pv[m][j] = perow[lane + 32 * j];
        }
        // ea rows are L1 hits; load inside the combine loop.
#pragma unroll
        for (int m = 0; m < ILP; m++) {
            const float* earow = ea + id[m] * D_EA;
            float* o = out + (base + m) * D_CONT;
#pragma unroll
            for (int j = 0; j < 4; j++) {
                int k = lane + 32 * j;
                o[k] = __ldg(earow + k) + __half2float(pv[m][j]);
            }
            if (lane == 0)
                o[D_EA] = __ldg(cont_vals + base + m) +
                          __half2float(g_pe129h[day[m] * P129H + D_EA]);
        }
    } else {
        // ---------------- categorical branch ----------------
        int g = gw - ngrp;
        if (g >= ngrp) return;
        int base = g * ILP;

        int boff[ILP], day[ILP], id[ILP];
#pragma unroll
        for (int m = 0; m < ILP; m++) {
            id[m]   = __ldg(categ_ids  + base + m);
            int v   = __ldg(categ_voc  + base + m);
            day[m]  = __ldg(categ_days + base + m);
            boff[m] = (id[m] * VOCAB + v) * 32 + lane;
        }

        // Front-batch the long-latency loads: table gather + PE rows.
        float4 b[ILP];
        uint2  p[ILP];
#pragma unroll
        for (int m = 0; m < ILP; m++) {
            b[m] = __ldg(tab4 + boff[m]);
            p[m] = *(reinterpret_cast<const uint2*>(g_pe128h) + day[m] * 32 + lane);
        }
        // ea rows are L1 hits; load inside the combine loop.
        const float4* ea4 = reinterpret_cast<const float4*>(ea);
#pragma unroll
        for (int m = 0; m < ILP; m++) {
            float4 a = __ldg(ea4 + id[m] * 32 + lane);
            __half2 p01 = *reinterpret_cast<__half2*>(&p[m].x);
            __half2 p23 = *reinterpret_cast<__half2*>(&p[m].y);
            float2 f01 = __half22float2(p01);
            float2 f23 = __half22float2(p23);
            float4 r;
            r.x = a.x + b[m].x + f01.x;
            r.y = a.y + b[m].y + f01.y;
            r.z = a.z + b[m].z + f23.x;
            r.w = a.w + b[m].w + f23.y;
            out_categ4[(base + m) * 32 + lane] = r;
        }
    }
}

// ---------------------------------------------------------------------------
// Generic fallback (tail-safe) — used only when n % ILP != 0.
// ---------------------------------------------------------------------------
__global__ __launch_bounds__(256, 5)
void k_main(const int* __restrict__ cont_ids,
            const float* __restrict__ cont_vals,
            const int* __restrict__ cont_days,
            const int* __restrict__ categ_ids,
            const int* __restrict__ categ_voc,
            const int* __restrict__ categ_days,
            const float* __restrict__ ea,
            const float4* __restrict__ tab4,
            float* __restrict__ out,
            float4* __restrict__ out_categ4,
            int n) {
    int gw   = (blockIdx.x * blockDim.x + threadIdx.x) >> 5;
    int lane = threadIdx.x & 31;
    int ngrp = (n + ILP - 1) / ILP;

    if (gw < ngrp) {
        int base = gw * ILP;
        int cnt  = n - base; if (cnt > ILP) cnt = ILP;
        int id[ILP], day[ILP];
#pragma unroll
        for (int m = 0; m < ILP; m++) {
            int w = (m < cnt) ? base + m : base;
            id[m]  = __ldg(cont_ids  + w);
            day[m] = __ldg(cont_days + w);
        }
        __half pv[ILP][4];
#pragma unroll
        for (int m = 0; m < ILP; m++) {
            const __half* perow = g_pe129h + day[m] * P129H;
#pragma unroll
            for (int j = 0; j < 4; j++)
                pv[m][j] = perow[lane + 32 * j];
        }
#pragma unroll
        for (int m = 0; m < ILP; m++) {
            if (m >= cnt) break;
            const float* earow = ea + id[m] * D_EA;
            float* o = out + (base + m) * D_CONT;
#pragma unroll
            for (int j = 0; j < 4; j++) {
                int k = lane + 32 * j;
                o[k] = __ldg(earow + k) + __half2float(pv[m][j]);
            }
            if (lane == 0)
                o[D_EA] = __ldg(cont_vals + base + m) +
                          __half2float(g_pe129h[day[m] * P129H + D_EA]);
        }
    } else {
        int g = gw - ngrp;
        if (g >= ngrp) return;
        int base = g * ILP;
        int cnt  = n - base; if (cnt > ILP) cnt = ILP;
        int id[ILP], v[ILP], day[ILP];
#pragma unroll
        for (int m = 0; m < ILP; m++) {
            int w = (m < cnt) ? base + m : base;
            id[m]  = __ldg(categ_ids  + w);
            v[m]   = __ldg(categ_voc  + w);
            day[m] = __ldg(categ_days + w);
        }
        float4 b[ILP];
        uint2  p[ILP];
#pragma unroll
        for (int m = 0; m < ILP; m++) {
            b[m] = __ldg(tab4 + (id[m] * VOCAB + v[m]) * 32 + lane);
            p[m] = *(reinterpret_cast<const uint2*>(g_pe128h) + day[m] * 32 + lane);
        }
        const float4* ea4 = reinterpret_cast<const float4*>(ea);
#pragma unroll
        for (int m = 0; m < ILP; m++) {
            if (m >= cnt) break;
            float4 a = __ldg(ea4 + id[m] * 32 + lane);
            __half2 p01 = *reinterpret_cast<__half2*>(&p[m].x);
            __half2 p23 = *reinterpret_cast<__half2*>(&p[m].y);
            float2 f01 = __half22float2(p01);
            float2 f23 = __half22float2(p23);
            float4 r;
            r.x = a.x + b[m].x + f01.x;
            r.y = a.y + b[m].y + f01.y;
            r.z = a.z + b[m].z + f23.x;
            r.w = a.w + b[m].w + f23.y;
            out_categ4[(base + m) * 32 + lane] = r;
        }
    }
}

// ---------------------------------------------------------------------------
// Scalar fallback kernels (used only if categ output offset is misaligned).
// ---------------------------------------------------------------------------
__global__ void k_cont(const int* __restrict__ ids,
                       const float* __restrict__ vals,
                       const int* __restrict__ days,
                       const float* __restrict__ ea,
                       float* __restrict__ out, int n) {
    int w    = (blockIdx.x * blockDim.x + threadIdx.x) >> 5;
    int lane = threadIdx.x & 31;
    if (w >= n) return;
    int id  = __ldg(ids  + w);
    int day = __ldg(days + w);
    const float*  earow = ea + id * D_EA;
    const __half* perow = g_pe129h + day * P129H;
    float* o = out + (long long)w * D_CONT;
#pragma unroll
    for (int j = 0; j < 4; j++) {
        int k = lane + 32 * j;
        o[k] = __ldg(earow + k) + __half2float(perow[k]);
    }
    if (lane == 0) o[D_EA] = __ldg(vals + w) + __half2float(perow[D_EA]);
}

__global__ void k_categ_scalar(const int* __restrict__ ids,
                               const int* __restrict__ vocab,
                               const int* __restrict__ days,
                               const float* __restrict__ ea,
                               const float* __restrict__ tab,
                               float* __restrict__ out, int n) {
    int w    = (blockIdx.x * blockDim.x + threadIdx.x) >> 5;
    int lane = threadIdx.x & 31;
    if (w >= n) return;
    int id  = __ldg(ids   + w);
    int v   = __ldg(vocab + w);
    int day = __ldg(days  + w);
    const float*  earow = ea + id * D_EA;
    const float*  trow  = tab + ((long long)id * VOCAB + v) * D_EA;
    const __half* perow = g_pe128h + day * D_EA;
    float* o = out + (long long)w * D_EA;
#pragma unroll
    for (int j = 0; j < 4; j++) {
        int k = lane + 32 * j;
        o[k] = __ldg(earow + k) + __ldg(trow + k) + __half2float(perow[k]);
    }
}

// ---------------------------------------------------------------------------
// Launch
// ---------------------------------------------------------------------------
extern "C" void kernel_launch(void* const* d_in, const int* in_sizes, int n_in,
                              void* d_out, int out_size) {
    const int*   cont_ids   = (const int*)  d_in[0];
    const float* cont_vals  = (const float*)d_in[1];
    const int*   cont_days  = (const int*)  d_in[2];
    const int*   categ_ids  = (const int*)  d_in[3];
    const int*   categ_voc  = (const int*)  d_in[4];
    const int*   categ_days = (const int*)  d_in[5];
    const float* ea_table   = (const float*)d_in[6];
    const float* categ_tab  = (const float*)d_in[7];

    const int n = in_sizes[0];

    float* out       = (float*)d_out;
    float* out_categ = out + (long long)n * D_CONT;

    // PE tables (fp16), single fused kernel: 129 blocks (one per dim-pair).
    k_pe<<<129, 256>>>();

    bool aligned = ((((long long)n * D_CONT) & 3) == 0) &&
                   ((((unsigned long long)(size_t)out_categ) & 15ULL) == 0ULL);
    if (aligned && (n % ILP) == 0) {
        long long ngrp  = n / ILP;
        long long warps = 2LL * ngrp;
        int blocks = (int)((warps + 7) / 8);
        k_main_full<<<blocks, 256>>>(cont_ids, cont_vals, cont_days,
                                     categ_ids, categ_voc, categ_days,
                                     ea_table, (const float4*)categ_tab,
                                     out, (float4*)out_categ, n);
    } else if (aligned) {
        long long ngrp  = (n + ILP - 1) / ILP;
        long long warps = 2LL * ngrp;
        int blocks = (int)((warps + 7) / 8);
        k_main<<<blocks, 256>>>(cont_ids, cont_vals, cont_days,
                                categ_ids, categ_voc, categ_days,
                                ea_table, (const float4*)categ_tab,
                                out, (float4*)out_categ, n);
    } else {
        int blocks = (n + 7) / 8;
        k_cont<<<blocks, 256>>>(cont_ids, cont_vals, cont_days, ea_table, out, n);
        k_categ_scalar<<<blocks, 256>>>(categ_ids, categ_voc, categ_days,
                                        ea_table, categ_tab, out_categ, n);
    }
}

// round 10
// speedup vs baseline: 2.0183x; 1.0357x over previous
#include <cuda_runtime.h>
#include <cuda_fp16.h>
#include <cstdint>

// ---------------------------------------------------------------------------
// Problem constants
// ---------------------------------------------------------------------------
#define N_TABLES 64
#define VOCAB    1024
#define D_EA     128
#define D_CONT   129
#define MAXDAY   3650
#define P129H    132          // half stride for pe129 rows: 264B, 8B-aligned
#define ILP      4            // nodes per warp

// ---------------------------------------------------------------------------
// Scratch (device globals; no allocation allowed)
// ---------------------------------------------------------------------------
__device__ __align__(16) __half g_pe129h[MAXDAY * P129H];   // ~0.96 MB
__device__ __align__(16) __half g_pe128h[MAXDAY * D_EA];    // ~0.93 MB

// ---------------------------------------------------------------------------
// PE table generation, one dim-pair per block (129 blocks). Thread 0 does
// the only double pow; 256 threads sweep 3650 days with integer
// fixed-point range reduction (q wraps mod 2^32 == exact mod 2*pi).
// ---------------------------------------------------------------------------
__global__ void k_pe() {
    __shared__ unsigned int s_theta;
    int pair = blockIdx.x;
    bool is129 = pair < 65;
    int j = is129 ? pair : pair - 65;

    if (threadIdx.x == 0) {
        int d = is129 ? D_CONT : D_EA;
        const double INV_TWO_PI = 0.15915494309189533576888376337251;
        double invdiv = pow(10000.0, -(double)(2 * j) / (double)d);
        double turns  = invdiv * INV_TWO_PI;
        double frac   = turns - floor(turns);
        unsigned long long q64 = (unsigned long long)(frac * 4294967296.0 + 0.5);
        s_theta = (unsigned int)q64;
    }
    __syncthreads();
    unsigned int theta = s_theta;

    const float SCALE = 1.46291807926715968e-09f;   // 2*pi / 2^32
    for (int day = threadIdx.x; day < MAXDAY; day += blockDim.x) {
        unsigned int q = (unsigned int)day * theta;
        float f = (float)(int)q * SCALE;
        float s, c;
        sincosf(f, &s, &c);
        if (is129) {
            if (j == 64) {
                g_pe129h[day * P129H + 128] = __float2half(s);  // k=128 even -> sin
            } else {
                *reinterpret_cast<__half2*>(&g_pe129h[day * P129H + 2 * j]) =
                    __floats2half2_rn(s, c);
            }
        } else {
            *reinterpret_cast<__half2*>(&g_pe128h[day * D_EA + 2 * j]) =
                __floats2half2_rn(s, c);
        }
    }
}

// ---------------------------------------------------------------------------
// Fused main kernel, FULL variant: requires n % ILP == 0 (no tail logic).
// ILP=4 nodes per warp, long-latency loads front-batched, ea rows (L1-
// resident 32KB) in the combine loop. launch_bounds(256,7) -> regs capped
// at 36 -> up to 56 warps/SM. Streaming (evict-first) stores keep the
// categ table + PE tables resident in L2.
// ---------------------------------------------------------------------------
__global__ __launch_bounds__(256, 7)
void k_main_full(const int* __restrict__ cont_ids,
                 const float* __restrict__ cont_vals,
                 const int* __restrict__ cont_days,
                 const int* __restrict__ categ_ids,
                 const int* __restrict__ categ_voc,
                 const int* __restrict__ categ_days,
                 const float* __restrict__ ea,
                 const float4* __restrict__ tab4,
                 float* __restrict__ out,
                 float4* __restrict__ out_categ4,
                 int n) {
    int gw   = (blockIdx.x * blockDim.x + threadIdx.x) >> 5;
    int lane = threadIdx.x & 31;
    int ngrp = n / ILP;

    if (gw < ngrp) {
        // ---------------- continuous branch ----------------
        int base = gw * ILP;

        int id[ILP], day[ILP];
#pragma unroll
        for (int m = 0; m < ILP; m++) {
            id[m]  = __ldg(cont_ids  + base + m);
            day[m] = __ldg(cont_days + base + m);
        }

        // Front-batch the L2-latency PE reads.
        __half pv[ILP][4];
#pragma unroll
        for (int m = 0; m < ILP; m++) {
            const __half* perow = g_pe129h + day[m] * P129H;
#pragma unroll
            for (int j = 0; j < 4; j++)
                pv[m][j] = perow[lane + 32 * j];
        }
        // ea rows are L1 hits; load inside the combine loop.
#pragma unroll
        for (int m = 0; m < ILP; m++) {
            const float* earow = ea + id[m] * D_EA;
            float* o = out + (base + m) * D_CONT;
#pragma unroll
            for (int j = 0; j < 4; j++) {
                int k = lane + 32 * j;
                __stcs(&o[k], __ldg(earow + k) + __half2float(pv[m][j]));
            }
            if (lane == 0)
                __stcs(&o[D_EA], __ldg(cont_vals + base + m) +
                                 __half2float(g_pe129h[day[m] * P129H + D_EA]));
        }
    } else {
        // ---------------- categorical branch ----------------
        int g = gw - ngrp;
        if (g >= ngrp) return;
        int base = g * ILP;

        // Fold voc/day into load offsets so they die at issue; keep id for ea.
        int id[ILP], poff[ILP], boff[ILP];
#pragma unroll
        for (int m = 0; m < ILP; m++) {
            id[m]   = __ldg(categ_ids  + base + m);
            boff[m] = (id[m] * VOCAB + __ldg(categ_voc + base + m)) * 32 + lane;
            poff[m] = __ldg(categ_days + base + m) * 32 + lane;
        }

        // Front-batch the long-latency loads: table gather + PE rows.
        float4 b[ILP];
        uint2  p[ILP];
#pragma unroll
        for (int m = 0; m < ILP; m++) {
            b[m] = __ldg(tab4 + boff[m]);
            p[m] = *(reinterpret_cast<const uint2*>(g_pe128h) + poff[m]);
        }
        // ea rows are L1 hits; load inside the combine loop.
        const float4* ea4 = reinterpret_cast<const float4*>(ea);
#pragma unroll
        for (int m = 0; m < ILP; m++) {
            float4 a = __ldg(ea4 + id[m] * 32 + lane);
            __half2 p01 = *reinterpret_cast<__half2*>(&p[m].x);
            __half2 p23 = *reinterpret_cast<__half2*>(&p[m].y);
            float2 f01 = __half22float2(p01);
            float2 f23 = __half22float2(p23);
            float4 r;
            r.x = a.x + b[m].x + f01.x;
            r.y = a.y + b[m].y + f01.y;
            r.z = a.z + b[m].z + f23.x;
            r.w = a.w + b[m].w + f23.y;
            __stcs(&out_categ4[(base + m) * 32 + lane], r);
        }
    }
}

// ---------------------------------------------------------------------------
// Generic fallback (tail-safe) — used only when n % ILP != 0.
// ---------------------------------------------------------------------------
__global__ __launch_bounds__(256, 5)
void k_main(const int* __restrict__ cont_ids,
            const float* __restrict__ cont_vals,
            const int* __restrict__ cont_days,
            const int* __restrict__ categ_ids,
            const int* __restrict__ categ_voc,
            const int* __restrict__ categ_days,
            const float* __restrict__ ea,
            const float4* __restrict__ tab4,
            float* __restrict__ out,
            float4* __restrict__ out_categ4,
            int n) {
    int gw   = (blockIdx.x * blockDim.x + threadIdx.x) >> 5;
    int lane = threadIdx.x & 31;
    int ngrp = (n + ILP - 1) / ILP;

    if (gw < ngrp) {
        int base = gw * ILP;
        int cnt  = n - base; if (cnt > ILP) cnt = ILP;
        int id[ILP], day[ILP];
#pragma unroll
        for (int m = 0; m < ILP; m++) {
            int w = (m < cnt) ? base + m : base;
            id[m]  = __ldg(cont_ids  + w);
            day[m] = __ldg(cont_days + w);
        }
        __half pv[ILP][4];
#pragma unroll
        for (int m = 0; m < ILP; m++) {
            const __half* perow = g_pe129h + day[m] * P129H;
#pragma unroll
            for (int j = 0; j < 4; j++)
                pv[m][j] = perow[lane + 32 * j];
        }
#pragma unroll
        for (int m = 0; m < ILP; m++) {
            if (m >= cnt) break;
            const float* earow = ea + id[m] * D_EA;
            float* o = out + (base + m) * D_CONT;
#pragma unroll
            for (int j = 0; j < 4; j++) {
                int k = lane + 32 * j;
                o[k] = __ldg(earow + k) + __half2float(pv[m][j]);
            }
            if (lane == 0)
                o[D_EA] = __ldg(cont_vals + base + m) +
                          __half2float(g_pe129h[day[m] * P129H + D_EA]);
        }
    } else {
        int g = gw - ngrp;
        if (g >= ngrp) return;
        int base = g * ILP;
        int cnt  = n - base; if (cnt > ILP) cnt = ILP;
        int id[ILP], v[ILP], day[ILP];
#pragma unroll
        for (int m = 0; m < ILP; m++) {
            int w = (m < cnt) ? base + m : base;
            id[m]  = __ldg(categ_ids  + w);
            v[m]   = __ldg(categ_voc  + w);
            day[m] = __ldg(categ_days + w);
        }
        float4 b[ILP];
        uint2  p[ILP];
#pragma unroll
        for (int m = 0; m < ILP; m++) {
            b[m] = __ldg(tab4 + (id[m] * VOCAB + v[m]) * 32 + lane);
            p[m] = *(reinterpret_cast<const uint2*>(g_pe128h) + day[m] * 32 + lane);
        }
        const float4* ea4 = reinterpret_cast<const float4*>(ea);
#pragma unroll
        for (int m = 0; m < ILP; m++) {
            if (m >= cnt) break;
            float4 a = __ldg(ea4 + id[m] * 32 + lane);
            __half2 p01 = *reinterpret_cast<__half2*>(&p[m].x);
            __half2 p23 = *reinterpret_cast<__half2*>(&p[m].y);
            float2 f01 = __half22float2(p01);
            float2 f23 = __half22float2(p23);
            float4 r;
            r.x = a.x + b[m].x + f01.x;
            r.y = a.y + b[m].y + f01.y;
            r.z = a.z + b[m].z + f23.x;
            r.w = a.w + b[m].w + f23.y;
            out_categ4[(base + m) * 32 + lane] = r;
        }
    }
}

// ---------------------------------------------------------------------------
// Scalar fallback kernels (used only if categ output offset is misaligned).
// ---------------------------------------------------------------------------
__global__ void k_cont(const int* __restrict__ ids,
                       const float* __restrict__ vals,
                       const int* __restrict__ days,
                       const float* __restrict__ ea,
                       float* __restrict__ out, int n) {
    int w    = (blockIdx.x * blockDim.x + threadIdx.x) >> 5;
    int lane = threadIdx.x & 31;
    if (w >= n) return;
    int id  = __ldg(ids  + w);
    int day = __ldg(days + w);
    const float*  earow = ea + id * D_EA;
    const __half* perow = g_pe129h + day * P129H;
    float* o = out + (long long)w * D_CONT;
#pragma unroll
    for (int j = 0; j < 4; j++) {
        int k = lane + 32 * j;
        o[k] = __ldg(earow + k) + __half2float(perow[k]);
    }
    if (lane == 0) o[D_EA] = __ldg(vals + w) + __half2float(perow[D_EA]);
}

__global__ void k_categ_scalar(const int* __restrict__ ids,
                               const int* __restrict__ vocab,
                               const int* __restrict__ days,
                               const float* __restrict__ ea,
                               const float* __restrict__ tab,
                               float* __restrict__ out, int n) {
    int w    = (blockIdx.x * blockDim.x + threadIdx.x) >> 5;
    int lane = threadIdx.x & 31;
    if (w >= n) return;
    int id  = __ldg(ids   + w);
    int v   = __ldg(vocab + w);
    int day = __ldg(days  + w);
    const float*  earow = ea + id * D_EA;
    const float*  trow  = tab + ((long long)id * VOCAB + v) * D_EA;
    const __half* perow = g_pe128h + day * D_EA;
    float* o = out + (long long)w * D_EA;
#pragma unroll
    for (int j = 0; j < 4; j++) {
        int k = lane + 32 * j;
        o[k] = __ldg(earow + k) + __ldg(trow + k) + __half2float(perow[k]);
    }
}

// ---------------------------------------------------------------------------
// Launch
// ---------------------------------------------------------------------------
extern "C" void kernel_launch(void* const* d_in, const int* in_sizes, int n_in,
                              void* d_out, int out_size) {
    const int*   cont_ids   = (const int*)  d_in[0];
    const float* cont_vals  = (const float*)d_in[1];
    const int*   cont_days  = (const int*)  d_in[2];
    const int*   categ_ids  = (const int*)  d_in[3];
    const int*   categ_voc  = (const int*)  d_in[4];
    const int*   categ_days = (const int*)  d_in[5];
    const float* ea_table   = (const float*)d_in[6];
    const float* categ_tab  = (const float*)d_in[7];

    const int n = in_sizes[0];

    float* out       = (float*)d_out;
    float* out_categ = out + (long long)n * D_CONT;

    // PE tables (fp16), single fused kernel: 129 blocks (one per dim-pair).
    k_pe<<<129, 256>>>();

    bool aligned = ((((long long)n * D_CONT) & 3) == 0) &&
                   ((((unsigned long long)(size_t)out_categ) & 15ULL) == 0ULL);
    if (aligned && (n % ILP) == 0) {
        long long ngrp  = n / ILP;
        long long warps = 2LL * ngrp;
        int blocks = (int)((warps + 7) / 8);
        k_main_full<<<blocks, 256>>>(cont_ids, cont_vals, cont_days,
                                     categ_ids, categ_voc, categ_days,
                                     ea_table, (const float4*)categ_tab,
                                     out, (float4*)out_categ, n);
    } else if (aligned) {
        long long ngrp  = (n + ILP - 1) / ILP;
        long long warps = 2LL * ngrp;
        int blocks = (int)((warps + 7) / 8);
        k_main<<<blocks, 256>>>(cont_ids, cont_vals, cont_days,
                                categ_ids, categ_voc, categ_days,
                                ea_table, (const float4*)categ_tab,
                                out, (float4*)out_categ, n);
    } else {
        int blocks = (n + 7) / 8;
        k_cont<<<blocks, 256>>>(cont_ids, cont_vals, cont_days, ea_table, out, n);
        k_categ_scalar<<<blocks, 256>>>(categ_ids, categ_voc, categ_days,
                                        ea_table, categ_tab, out_categ, n);
    }
}